// round 10
// baseline (speedup 1.0000x reference)
#include <cuda_runtime.h>
#include <cuda_fp16.h>
#include <math.h>
#include <stdint.h>

#define BSZ 2
#define SEQ 2048
#define EMB 1024
#define NH  16
#define HD  64

// ---------------------------------------------------------------------------
// Scratch (__device__ globals)
// ---------------------------------------------------------------------------
__device__ __half g_xh[(size_t)BSZ * SEQ * EMB];
__device__ __half g_w1h[(size_t)3 * EMB * EMB];
__device__ __half g_w2h[(size_t)EMB * EMB];
__device__ __half g_qkvh[(size_t)BSZ * SEQ * 3 * EMB];
__device__ __half g_ah[(size_t)BSZ * SEQ * EMB];

// ---------------------------------------------------------------------------
// fp32 -> fp16 convert
// ---------------------------------------------------------------------------
__global__ __launch_bounds__(256) void conv_kernel(
    const float4* __restrict__ in, uint2* __restrict__ hi, int n4)
{
    int i = blockIdx.x * blockDim.x + threadIdx.x;
    if (i >= n4) return;
    float4 v = in[i];
    __half2 a(__float2half_rn(v.x), __float2half_rn(v.y));
    __half2 b(__float2half_rn(v.z), __float2half_rn(v.w));
    uint2 H;
    H.x = *reinterpret_cast<uint32_t*>(&a);
    H.y = *reinterpret_cast<uint32_t*>(&b);
    hi[i] = H;
}

// ---------------------------------------------------------------------------
// MMA / cp.async helpers
// ---------------------------------------------------------------------------
__device__ __forceinline__ void ldsm4(uint32_t a, uint32_t& r0, uint32_t& r1,
                                      uint32_t& r2, uint32_t& r3)
{
    asm volatile("ldmatrix.sync.aligned.m8n8.x4.shared.b16 {%0,%1,%2,%3}, [%4];\n"
                 : "=r"(r0), "=r"(r1), "=r"(r2), "=r"(r3) : "r"(a));
}
__device__ __forceinline__ void ldsm4t(uint32_t a, uint32_t& r0, uint32_t& r1,
                                       uint32_t& r2, uint32_t& r3)
{
    asm volatile("ldmatrix.sync.aligned.m8n8.x4.trans.shared.b16 {%0,%1,%2,%3}, [%4];\n"
                 : "=r"(r0), "=r"(r1), "=r"(r2), "=r"(r3) : "r"(a));
}
__device__ __forceinline__ void mma16816(float* d, const uint32_t* a, const uint32_t* b)
{
    asm volatile("mma.sync.aligned.m16n8k16.row.col.f32.f16.f16.f32 "
                 "{%0,%1,%2,%3}, {%4,%5,%6,%7}, {%8,%9}, {%0,%1,%2,%3};\n"
                 : "+f"(d[0]), "+f"(d[1]), "+f"(d[2]), "+f"(d[3])
                 : "r"(a[0]), "r"(a[1]), "r"(a[2]), "r"(a[3]), "r"(b[0]), "r"(b[1]));
}
__device__ __forceinline__ uint32_t pack_h(float a, float b)
{
    __half2 p(__float2half_rn(a), __float2half_rn(b));
    return *reinterpret_cast<uint32_t*>(&p);
}
__device__ __forceinline__ void cp16(uint32_t saddr, const void* gaddr)
{
    asm volatile("cp.async.cg.shared.global [%0], [%1], 16;" :: "r"(saddr), "l"(gaddr));
}
#define CP_COMMIT() asm volatile("cp.async.commit_group;" ::: "memory")
#define CP_WAIT1()  asm volatile("cp.async.wait_group 1;" ::: "memory")
#define CP_WAIT0()  asm volatile("cp.async.wait_group 0;" ::: "memory")

// ---------------------------------------------------------------------------
// Pure fp16 GEMM:  C = A·B^T + bias
// CTA 128(M) x 256(N), 8 warps (2m x 4n), warp tile 64x64.
// Per ks-burst: 8 LDSM -> 32 MMAs (4:1 ratio, the R7-proven density).
// K-chunks of 64, 2-stage cp.async. 1 CTA/SM (regs ~185, smem 108 KB).
// ---------------------------------------------------------------------------
#define SAST 72
#define GA_BYTES (128 * SAST * 2)       // 18432
#define GB_BYTES (256 * SAST * 2)       // 36864
#define GSTG_B   (GA_BYTES + GB_BYTES)  // 55296
#define GEMM_SMEM (2 * GSTG_B)          // 110592

template<bool HALF_OUT>
__global__ __launch_bounds__(256) void mma_gemm_bias(
    const __half* __restrict__ Ah, const __half* __restrict__ Bh,
    const float* __restrict__ bias, float* __restrict__ Cf,
    __half* __restrict__ Ch,
    int M, int N, int K)
{
    extern __shared__ __align__(16) unsigned char gsm[];
    const uint32_t sb = (uint32_t)__cvta_generic_to_shared(gsm);

    const int tid = threadIdx.x, lane = tid & 31, wid = tid >> 5;
    const int wm = (wid >> 2) * 64;     // 0,64
    const int wn = (wid & 3) * 64;      // 0,64,128,192
    const int m0 = blockIdx.y * 128, n0 = blockIdx.x * 256;

    // A loads: thread t -> row t>>1, col half (t&1)*16 (+32 offset pair)
    const int lrow = tid >> 1;
    const int lcol = (tid & 1) * 16;
    const uint32_t soA = (uint32_t)(lrow * SAST + lcol) * 2;
    const __half* gA = Ah + (size_t)(m0 + lrow) * K + lcol;
    // B loads: thread t -> row t (0..255), all 64 cols
    const uint32_t soB = GA_BYTES + (uint32_t)tid * SAST * 2;
    const __half* gB = Bh + (size_t)(n0 + tid) * K;

    const int aoff = ((wm + (lane & 15)) * SAST + (lane >> 4) * 8) * 2;
    const int boff = ((wn + (lane & 7) + ((lane >> 4) & 1) * 8) * SAST
                      + ((lane >> 3) & 1) * 8) * 2;

    float acc[4][8][4];
    #pragma unroll
    for (int i = 0; i < 4; ++i)
        #pragma unroll
        for (int j = 0; j < 8; ++j)
            acc[i][j][0] = acc[i][j][1] = acc[i][j][2] = acc[i][j][3] = 0.f;

    const int NCH = K / 64;

    auto load_stage = [&](int c, int st) {
        const int kc = c * 64;
        const uint32_t baseA = sb + st * GSTG_B + soA;
        cp16(baseA,      gA + kc);
        cp16(baseA + 16, gA + kc + 8);
        cp16(baseA + 64, gA + kc + 32);
        cp16(baseA + 80, gA + kc + 40);
        const uint32_t baseB = sb + st * GSTG_B + soB;
        #pragma unroll
        for (int j = 0; j < 8; ++j)
            cp16(baseB + j * 16, gB + kc + j * 8);
        CP_COMMIT();
    };

    load_stage(0, 0);
    load_stage(1, 1);

    for (int c = 0; c < NCH; ++c) {
        if (c == NCH - 1) { CP_WAIT0(); } else { CP_WAIT1(); }
        __syncthreads();

        const int st = c & 1;
        const uint32_t bA = sb + st * GSTG_B;
        const uint32_t bB = bA + GA_BYTES;

        #pragma unroll
        for (int ks = 0; ks < 4; ++ks) {
            const int kb = ks * 32;
            uint32_t a[4][4], bfr[8][2];
            #pragma unroll
            for (int mi = 0; mi < 4; ++mi) {
                const int mo = mi * 16 * SAST * 2 + kb;
                ldsm4(bA + aoff + mo, a[mi][0], a[mi][1], a[mi][2], a[mi][3]);
            }
            #pragma unroll
            for (int nj = 0; nj < 4; ++nj) {
                const int no = nj * 16 * SAST * 2 + kb;
                uint32_t t0, t1, t2, t3;
                ldsm4(bB + boff + no, t0, t1, t2, t3);
                bfr[nj * 2][0] = t0; bfr[nj * 2][1] = t1;
                bfr[nj * 2 + 1][0] = t2; bfr[nj * 2 + 1][1] = t3;
            }
            #pragma unroll
            for (int mi = 0; mi < 4; ++mi)
                #pragma unroll
                for (int ni = 0; ni < 8; ++ni)
                    mma16816(acc[mi][ni], a[mi], bfr[ni]);
        }
        __syncthreads();
        if (c + 2 < NCH) load_stage(c + 2, st);
    }

    const int rbase = m0 + wm + (lane >> 2);
    const int cbase = n0 + wn + (lane & 3) * 2;
    #pragma unroll
    for (int mi = 0; mi < 4; ++mi) {
        const int r = rbase + mi * 16;
        #pragma unroll
        for (int ni = 0; ni < 8; ++ni) {
            const int c = cbase + ni * 8;
            const float b0 = bias[c], b1 = bias[c + 1];
            const float v0 = acc[mi][ni][0] + b0, v1 = acc[mi][ni][1] + b1;
            const float v2 = acc[mi][ni][2] + b0, v3 = acc[mi][ni][3] + b1;
            if (HALF_OUT) {
                *(uint32_t*)&Ch[(size_t)r * N + c]       = pack_h(v0, v1);
                *(uint32_t*)&Ch[(size_t)(r + 8) * N + c] = pack_h(v2, v3);
            } else {
                float2 o0 = { v0, v1 }, o1 = { v2, v3 };
                *(float2*)&Cf[(size_t)r * N + c] = o0;
                *(float2*)&Cf[(size_t)(r + 8) * N + c] = o1;
            }
        }
    }
}

// ---------------------------------------------------------------------------
// fp16 flash attention, BM=128 q-rows per CTA (256 thr, 8 warps), KV tile 64.
// Each K/V smem tile feeds 2x the MMAs vs BM=64: loads/syncs per MMA halved.
// Causal mask applied on the last two KV tiles (doff = j0*64 - q0 in {0,64}).
// ---------------------------------------------------------------------------
#define FST 72
#define FLASH_SMEM ((128 + 64 + 64) * FST * 2)   // 36864

__global__ __launch_bounds__(256) void flash_mma(
    const __half* __restrict__ qkvh, __half* __restrict__ attn)
{
    extern __shared__ __half fsm[];
    __half* sQ = fsm;                    // [128][FST]
    __half* sK = fsm + 128 * FST;        // [64][FST]
    __half* sV = fsm + 192 * FST;        // [64][FST]

    const int b = blockIdx.z, h = blockIdx.y;
    const int qtt = gridDim.x - 1 - blockIdx.x;   // long tiles first
    const int tid = threadIdx.x, lane = tid & 31, wid = tid >> 5;
    const size_t bbase = (size_t)b * SEQ * 3 * EMB;
    const int hbase = h * SEQ * HD;
    const int q0 = qtt * 128;

    // stage Q (128x64)
    #pragma unroll
    for (int i = 0; i < 4; ++i) {
        const int id = tid + 256 * i;            // 0..1023
        const int r = id >> 3, c = (id & 7) * 8;
        const int f = hbase + (q0 + r) * HD + c;
        const size_t ga = bbase + (size_t)(f >> 10) * 3072 + (f & 1023);
        *(uint4*)&sQ[r * FST + c] = *(const uint4*)&qkvh[ga];
    }
    __syncthreads();

    const uint32_t bQ = (uint32_t)__cvta_generic_to_shared(sQ);
    const uint32_t bK = (uint32_t)__cvta_generic_to_shared(sK);
    const uint32_t bV = (uint32_t)__cvta_generic_to_shared(sV);

    const int aoff = ((wid * 16 + (lane & 15)) * FST + (lane >> 4) * 8) * 2;
    uint32_t qf[4][4];
    #pragma unroll
    for (int kt = 0; kt < 4; ++kt)
        ldsm4(bQ + aoff + kt * 32, qf[kt][0], qf[kt][1], qf[kt][2], qf[kt][3]);

    const int boffK = (((lane & 7) + ((lane >> 4) & 1) * 8) * FST + ((lane >> 3) & 1) * 8) * 2;
    const int voffV = (((lane & 7) + ((lane >> 3) & 1) * 8) * FST + (lane >> 4) * 8) * 2;

    float m_r[2] = { -INFINITY, -INFINITY };
    float l_r[2] = { 0.f, 0.f };
    float oacc[8][4];
    #pragma unroll
    for (int nt = 0; nt < 8; ++nt)
        oacc[nt][0] = oacc[nt][1] = oacc[nt][2] = oacc[nt][3] = 0.f;

    const int rloc = wid * 16 + (lane >> 2);   // 0..127 (and +8)
    const int cloc = 2 * (lane & 3);

    const int jmax = 2 * qtt + 1;
    for (int j0 = 0; j0 <= jmax; ++j0) {
        __syncthreads();
        #pragma unroll
        for (int i = 0; i < 2; ++i) {
            const int id = tid + 256 * i;            // 0..511
            const int r = id >> 3, c = (id & 7) * 8;
            const int f = hbase + (j0 * 64 + r) * HD + c;
            const size_t ga = bbase + (size_t)(f >> 10) * 3072 + (f & 1023);
            *(uint4*)&sK[r * FST + c] = *(const uint4*)&qkvh[ga + 1024];
            *(uint4*)&sV[r * FST + c] = *(const uint4*)&qkvh[ga + 2048];
        }
        __syncthreads();

        float sacc[8][4];
        #pragma unroll
        for (int nt = 0; nt < 8; ++nt)
            sacc[nt][0] = sacc[nt][1] = sacc[nt][2] = sacc[nt][3] = 0.f;

        #pragma unroll
        for (int kt = 0; kt < 4; ++kt) {
            #pragma unroll
            for (int nj = 0; nj < 4; ++nj) {
                uint32_t h0, h1, h2, h3;
                const int off = nj * 16 * FST * 2 + kt * 32;
                ldsm4(bK + boffK + off, h0, h1, h2, h3);
                uint32_t bh0[2] = { h0, h1 }, bh1[2] = { h2, h3 };
                mma16816(sacc[nj * 2], qf[kt], bh0);
                mma16816(sacc[nj * 2 + 1], qf[kt], bh1);
            }
        }

        #pragma unroll
        for (int nt = 0; nt < 8; ++nt) {
            sacc[nt][0] *= 0.125f; sacc[nt][1] *= 0.125f;
            sacc[nt][2] *= 0.125f; sacc[nt][3] *= 0.125f;
        }
        if (j0 >= 2 * qtt) {               // diagonal region (last two tiles)
            const int doff = j0 * 64 - q0;  // 0 or 64
            #pragma unroll
            for (int nt = 0; nt < 8; ++nt) {
                const int jc = doff + nt * 8 + cloc;
                if (jc > rloc)     sacc[nt][0] = -INFINITY;
                if (jc + 1 > rloc) sacc[nt][1] = -INFINITY;
                if (jc > rloc + 8)     sacc[nt][2] = -INFINITY;
                if (jc + 1 > rloc + 8) sacc[nt][3] = -INFINITY;
            }
        }
        float mx0 = -INFINITY, mx1 = -INFINITY;
        #pragma unroll
        for (int nt = 0; nt < 8; ++nt) {
            mx0 = fmaxf(mx0, fmaxf(sacc[nt][0], sacc[nt][1]));
            mx1 = fmaxf(mx1, fmaxf(sacc[nt][2], sacc[nt][3]));
        }
        mx0 = fmaxf(mx0, __shfl_xor_sync(0xffffffffu, mx0, 1));
        mx0 = fmaxf(mx0, __shfl_xor_sync(0xffffffffu, mx0, 2));
        mx1 = fmaxf(mx1, __shfl_xor_sync(0xffffffffu, mx1, 1));
        mx1 = fmaxf(mx1, __shfl_xor_sync(0xffffffffu, mx1, 2));
        const float mn0 = fmaxf(m_r[0], mx0), mn1 = fmaxf(m_r[1], mx1);
        const float al0 = __expf(m_r[0] - mn0), al1 = __expf(m_r[1] - mn1);
        m_r[0] = mn0; m_r[1] = mn1;

        float rs0 = 0.f, rs1 = 0.f;
        #pragma unroll
        for (int nt = 0; nt < 8; ++nt) {
            sacc[nt][0] = __expf(sacc[nt][0] - mn0); rs0 += sacc[nt][0];
            sacc[nt][1] = __expf(sacc[nt][1] - mn0); rs0 += sacc[nt][1];
            sacc[nt][2] = __expf(sacc[nt][2] - mn1); rs1 += sacc[nt][2];
            sacc[nt][3] = __expf(sacc[nt][3] - mn1); rs1 += sacc[nt][3];
        }
        rs0 += __shfl_xor_sync(0xffffffffu, rs0, 1);
        rs0 += __shfl_xor_sync(0xffffffffu, rs0, 2);
        rs1 += __shfl_xor_sync(0xffffffffu, rs1, 1);
        rs1 += __shfl_xor_sync(0xffffffffu, rs1, 2);
        l_r[0] = l_r[0] * al0 + rs0;
        l_r[1] = l_r[1] * al1 + rs1;
        #pragma unroll
        for (int nt = 0; nt < 8; ++nt) {
            oacc[nt][0] *= al0; oacc[nt][1] *= al0;
            oacc[nt][2] *= al1; oacc[nt][3] *= al1;
        }

        #pragma unroll
        for (int kt = 0; kt < 4; ++kt) {
            uint32_t ph[4];
            ph[0] = pack_h(sacc[2 * kt][0], sacc[2 * kt][1]);
            ph[1] = pack_h(sacc[2 * kt][2], sacc[2 * kt][3]);
            ph[2] = pack_h(sacc[2 * kt + 1][0], sacc[2 * kt + 1][1]);
            ph[3] = pack_h(sacc[2 * kt + 1][2], sacc[2 * kt + 1][3]);
            #pragma unroll
            for (int nj = 0; nj < 4; ++nj) {
                uint32_t v0, v1, v2, v3;
                const int off = kt * 16 * FST * 2 + nj * 32;
                ldsm4t(bV + voffV + off, v0, v1, v2, v3);
                uint32_t vh0[2] = { v0, v1 }, vh1[2] = { v2, v3 };
                mma16816(oacc[nj * 2], ph, vh0);
                mma16816(oacc[nj * 2 + 1], ph, vh1);
            }
        }
    }

    const float inv0 = 1.f / l_r[0], inv1 = 1.f / l_r[1];
    const int qrow = q0 + rloc;
    #pragma unroll
    for (int nt = 0; nt < 8; ++nt) {
        const int col = h * HD + nt * 8 + cloc;
        const float v0 = oacc[nt][0] * inv0, v1 = oacc[nt][1] * inv0;
        const float v2 = oacc[nt][2] * inv1, v3 = oacc[nt][3] * inv1;
        const size_t r0 = ((size_t)b * SEQ + qrow) * EMB + col;
        const size_t r1 = ((size_t)b * SEQ + qrow + 8) * EMB + col;
        *(uint32_t*)&attn[r0] = pack_h(v0, v1);
        *(uint32_t*)&attn[r1] = pack_h(v2, v3);
    }
}

// ---------------------------------------------------------------------------
extern "C" void kernel_launch(void* const* d_in, const int* in_sizes, int n_in,
                              void* d_out, int out_size)
{
    const float* x    = (const float*)d_in[0];
    const float* Wqkv = (const float*)d_in[1];
    const float* bqkv = (const float*)d_in[2];
    const float* Wout = (const float*)d_in[3];
    const float* bout = (const float*)d_in[4];
    float* out = (float*)d_out;

    __half *xh, *w1h, *w2h, *qkvh, *ah;
    cudaGetSymbolAddress((void**)&xh, g_xh);
    cudaGetSymbolAddress((void**)&w1h, g_w1h);
    cudaGetSymbolAddress((void**)&w2h, g_w2h);
    cudaGetSymbolAddress((void**)&qkvh, g_qkvh);
    cudaGetSymbolAddress((void**)&ah, g_ah);

    cudaFuncSetAttribute(flash_mma,
                         cudaFuncAttributeMaxDynamicSharedMemorySize, FLASH_SMEM);
    cudaFuncSetAttribute(mma_gemm_bias<true>,
                         cudaFuncAttributeMaxDynamicSharedMemorySize, GEMM_SMEM);
    cudaFuncSetAttribute(mma_gemm_bias<false>,
                         cudaFuncAttributeMaxDynamicSharedMemorySize, GEMM_SMEM);

    const int nx  = BSZ * SEQ * EMB;
    const int nw1 = 3 * EMB * EMB;
    const int nw2 = EMB * EMB;

    // 0) fp32 -> fp16 conversions
    conv_kernel<<<nx / 4 / 256, 256>>>((const float4*)x, (uint2*)xh, nx / 4);
    conv_kernel<<<nw1 / 4 / 256, 256>>>((const float4*)Wqkv, (uint2*)w1h, nw1 / 4);
    conv_kernel<<<nw2 / 4 / 256, 256>>>((const float4*)Wout, (uint2*)w2h, nw2 / 4);

    // 1) qkv = x @ Wqkv^T + bqkv  -> fp16
    mma_gemm_bias<true><<<dim3(3 * EMB / 256, BSZ * SEQ / 128), 256, GEMM_SMEM>>>(
        xh, w1h, bqkv, nullptr, qkvh, BSZ * SEQ, 3 * EMB, EMB);

    // 2) causal flash attention -> attn fp16
    flash_mma<<<dim3(SEQ / 128, NH, BSZ), 256, FLASH_SMEM>>>(qkvh, ah);

    // 3) out = attn @ Wout^T + bout  (fp32 out)
    mma_gemm_bias<false><<<dim3(EMB / 256, BSZ * SEQ / 128), 256, GEMM_SMEM>>>(
        ah, w2h, bout, out, nullptr, BSZ * SEQ, EMB, EMB);
}